// round 15
// baseline (speedup 1.0000x reference)
#include <cuda_runtime.h>
#include <cuda_bf16.h>
#include <cuda_fp16.h>
#include <cstdint>
#include <math.h>
#define DIM 1024
#define TOK 4096
#define MA 32768
#define NU 34
#define FDIM 4096
#define SCL 0.03125f
typedef __nv_bfloat16 bf16;

__device__ float g_CA[(size_t)MA*DIM];
__device__ float g_G [(size_t)MA*NU];
__device__ float g_CB[(size_t)TOK*32];
__device__ float g_U [(size_t)NU*DIM];
__device__ float g_pbv[32], g_c0[1];
__device__ __align__(256) __half e_A [(size_t)MA*2*DIM];   // fp16 A2 (h,l)
__device__ __align__(256) __half e_CU[(size_t)1152*DIM];   // fp16 plain: rows 0-1023 C, 1024-1057 U'
__device__ __align__(256) bf16 e_Wq[(size_t)DIM*3*DIM];
__device__ __align__(256) bf16 e_Wk[(size_t)DIM*3*DIM];
__device__ __align__(256) bf16 e_cx[(size_t)TOK*3*DIM];
__device__ __align__(256) bf16 e_Pq[(size_t)32*3*DIM];
__device__ __align__(256) __half e_Z [(size_t)TOK*2*DIM];   // fp16 A2
__device__ __align__(256) __half e_Wv[(size_t)DIM*DIM];     // fp16 plain
__device__ __align__(256) __half e_CO[(size_t)TOK*2*DIM];   // fp16 A2
__device__ __align__(256) __half e_Wu[(size_t)FDIM*DIM];    // fp16 plain
__device__ __align__(256) __half e_H [(size_t)TOK*2*FDIM];  // fp16 A2
__device__ __align__(256) __half e_Wd[(size_t)DIM*FDIM];    // fp16 plain

__device__ __forceinline__ uint32_t smem_u32(const void* p){
  uint32_t a;
  asm("{ .reg .u64 t; cvta.to.shared.u64 t, %1; cvt.u32.u64 %0, t; }" : "=r"(a) : "l"(p));
  return a;
}
__device__ __forceinline__ void cpa16(uint32_t s, const void* g){
  asm volatile("cp.async.cg.shared.global [%0], [%1], 16;\n" :: "r"(s), "l"(g));
}
// DT 0=bf16, 1=fp16
template<int DT>
__device__ __forceinline__ void mma_t(float c[4], const uint32_t a[4], const uint32_t b[2]){
  if (DT==0)
    asm volatile(
      "mma.sync.aligned.m16n8k16.row.col.f32.bf16.bf16.f32 "
      "{%0,%1,%2,%3}, {%4,%5,%6,%7}, {%8,%9}, {%0,%1,%2,%3};\n"
      : "+f"(c[0]), "+f"(c[1]), "+f"(c[2]), "+f"(c[3])
      : "r"(a[0]), "r"(a[1]), "r"(a[2]), "r"(a[3]), "r"(b[0]), "r"(b[1]));
  else
    asm volatile(
      "mma.sync.aligned.m16n8k16.row.col.f32.f16.f16.f32 "
      "{%0,%1,%2,%3}, {%4,%5,%6,%7}, {%8,%9}, {%0,%1,%2,%3};\n"
      : "+f"(c[0]), "+f"(c[1]), "+f"(c[2]), "+f"(c[3])
      : "r"(a[0]), "r"(a[1]), "r"(a[2]), "r"(a[3]), "r"(b[0]), "r"(b[1]));
}
#define LDSM4(r, a) \
  asm volatile("ldmatrix.sync.aligned.m8n8.x4.shared.b16 {%0,%1,%2,%3}, [%4];" \
    : "=r"((r)[0]),"=r"((r)[1]),"=r"((r)[2]),"=r"((r)[3]) : "r"(a))
__device__ __forceinline__ void bsp(float v, bf16 &h, bf16 &l){
  h = __float2bfloat16_rn(v); l = __float2bfloat16_rn(v - __bfloat162float(h));
}
__device__ __forceinline__ void hsp(float v, __half &h, __half &l){
  h = __float2half_rn(v); l = __float2half_rn(v - __half2float(h));
}

// EPI: 0 fp32 | 1 fp16-plain | 5 +bias->fp32 | 6 split CA/G fp32 | 7 +bias+X2->fp16A2 | 8 gelu(+bias)->fp16A2
template<int EPI>
__device__ __forceinline__ void emit(float v, int m, int col, int N,
                                     float* Cf, float* Cf2, bf16* Ce,
                                     const float* bias, const float* X2){
  if (EPI==6){
    if (col < DIM) Cf[(size_t)m*DIM + col] = v;
    else Cf2[(size_t)m*NU + (col-DIM)] = v;
    return;
  }
  if (EPI==1){ ((__half*)Ce)[(size_t)m*N + col] = __float2half_rn(v); return; }
  if (EPI==5){ Cf[(size_t)m*N + col] = v + bias[col]; return; }
  if (EPI==0){ Cf[(size_t)m*N + col] = v; return; }
  // 7 / 8: fp16 A2 (h,l), row stride 2N
  if (EPI==7) v += bias[col] + X2[(size_t)m*N + col];
  else { v += bias[col]; v = 0.5f*v*(1.0f + erff(v*0.70710678f)); }
  __half h, l; hsp(v, h, l);
  __half* E = (__half*)Ce;
  size_t b = (size_t)m*2*N;
  E[b + col] = h; E[b + N + col] = l;
}

// C[m,n] = sum over Ka of A[m,k]*B[n,k mod Kb]; 2-byte K-major operands.
// 3-stage cp.async, ldmatrix, 144B rows. Ka%64==0, Kb%64==0, Ka<=2*Kb.
template<int BN, int DT, int EPI>
__global__ __launch_bounds__(256,2)
void lg_k(const void* __restrict__ Av, const void* __restrict__ Bv,
          int Ka, int Kb, int N, int Nb,
          float* __restrict__ Cf, float* __restrict__ Cf2, bf16* __restrict__ Ce,
          const float* __restrict__ bias, const float* __restrict__ X2)
{
  const bf16* A = (const bf16*)Av; const bf16* B = (const bf16*)Bv;
  constexpr int ROWB  = 144;
  constexpr int ATILEB= 128*ROWB;
  constexpr int STAGEB= (128+BN)*ROWB;
  constexpr int CHT   = (128+BN)*8/256;
  constexpr int WN    = BN/2;
  constexpr int NT2   = WN/16;
  extern __shared__ __align__(16) char smraw[];
  const int tid = threadIdx.x;
  const int mBase = blockIdx.y*128, nBase = blockIdx.x*BN;
  const uint32_t smu = smem_u32(smraw);
  const int nK = Ka/64;

  uint32_t choff[CHT]; const bf16* gp[CHT]; bool val[CHT], isA_[CHT];
#pragma unroll
  for (int i=0;i<CHT;i++){
    const int c = tid + i*256;
    const int row = c>>3, kc = c&7;
    const bool isA = row < 128;
    const int lrow = isA ? row : row-128;
    choff[i] = (isA ? 0 : ATILEB) + lrow*ROWB + kc*16;
    const int gr = isA ? (mBase+row) : (nBase+lrow);
    gp[i] = (isA ? A + (size_t)gr*Ka : B + (size_t)gr*Kb) + kc*8;
    isA_[i] = isA;
    val[i] = isA || (nBase+lrow) < Nb;
    if (!val[i]){
      uint4 z = {0u,0u,0u,0u};
#pragma unroll
      for (int st=0; st<3; st++) *(uint4*)(smraw + st*STAGEB + choff[i]) = z;
    }
  }
  auto loadStage = [&](int st){
    if (st < nK){
      const uint32_t b = smu + (st%3)*STAGEB;
      const int koA = st*64;
      const int koB = (koA >= Kb) ? koA - Kb : koA;
#pragma unroll
      for (int i=0;i<CHT;i++) if (val[i]) cpa16(b + choff[i], gp[i] + (isA_[i]?koA:koB));
    }
    asm volatile("cp.async.commit_group;\n":::"memory");
  };

  float acc[2][WN/8][4];
#pragma unroll
  for (int a=0;a<2;a++)
#pragma unroll
    for (int b=0;b<WN/8;b++)
#pragma unroll
      for (int c=0;c<4;c++) acc[a][b][c]=0.f;

  const int warp = tid>>5, lane = tid&31;
  const int wm = (warp>>1)*32, wn = (warp&1)*WN;
  uint32_t aoff[2], boff[NT2];
#pragma unroll
  for (int mt=0;mt<2;mt++)
    aoff[mt] = (uint32_t)(wm + mt*16 + (lane&7) + ((lane>>3)&1)*8)*ROWB + ((lane>>4)&1)*16;
#pragma unroll
  for (int n2=0;n2<NT2;n2++)
    boff[n2] = ATILEB + (uint32_t)(wn + n2*16 + (lane&7) + ((lane>>4)&1)*8)*ROWB + ((lane>>3)&1)*16;

  loadStage(0); loadStage(1);
  for (int kt=0; kt<nK; ++kt){
    asm volatile("cp.async.wait_group 1;\n":::"memory");
    __syncthreads();
    loadStage(kt+2);
    const uint32_t base = smu + (kt%3)*STAGEB;
#pragma unroll
    for (int ks=0; ks<4; ++ks){
      const uint32_t ko = ks*32;
      uint32_t a[2][4];
#pragma unroll
      for (int mt=0;mt<2;mt++) LDSM4(a[mt], base + aoff[mt] + ko);
#pragma unroll
      for (int n2=0;n2<NT2;n2++){
        uint32_t b[4];
        LDSM4(b, base + boff[n2] + ko);
#pragma unroll
        for (int mt=0;mt<2;mt++){
          mma_t<DT>(acc[mt][2*n2],   a[mt], b);
          mma_t<DT>(acc[mt][2*n2+1], a[mt], b+2);
        }
      }
    }
  }

  const int r = lane>>2, c2 = (lane&3)*2;
#pragma unroll
  for (int mt=0;mt<2;mt++){
#pragma unroll
    for (int nt=0; nt<WN/8; nt++){
      const int row = mBase + wm + mt*16 + r;
      const int col = nBase + wn + nt*8 + c2;
      if (col < N){
        emit<EPI>(acc[mt][nt][0], row, col, N, Cf, Cf2, Ce, bias, X2);
        emit<EPI>(acc[mt][nt][2], row+8, col, N, Cf, Cf2, Ce, bias, X2);
      }
      if (col+1 < N){
        emit<EPI>(acc[mt][nt][1], row, col+1, N, Cf, Cf2, Ce, bias, X2);
        emit<EPI>(acc[mt][nt][3], row+8, col+1, N, Cf, Cf2, Ce, bias, X2);
      }
    }
  }
}

// MODE: 0 bf16 Aext(h,l,h) stride3C | 1 bf16 Bext(h,h,l) stride3C | 2 fp16 A2(h,l) stride2C | 3 fp16 plain strideC
template<int MODE>
__global__ __launch_bounds__(256)
void conv_k(const float* __restrict__ S, void* __restrict__ Ep, int C, long n4){
  long i = (long)blockIdx.x*256 + threadIdx.x;
  if (i >= n4) return;
  int c4 = C/4;
  int r = (int)(i / c4), cc = (int)(i % c4) * 4;
  float4 v = ((const float4*)S)[i];
  float vv[4] = {v.x, v.y, v.z, v.w};
  if (MODE<=1){
    bf16* E = (bf16*)Ep;
    bf16 h[4], l[4];
#pragma unroll
    for (int u=0;u<4;u++) bsp(vv[u], h[u], l[u]);
    uint2 ph = *(uint2*)h, pl = *(uint2*)l;
    size_t b = (size_t)r*3*C + cc;
    *(uint2*)(E + b)       = ph;
    *(uint2*)(E + b + C)   = (MODE==0) ? pl : ph;
    *(uint2*)(E + b + 2*C) = (MODE==0) ? ph : pl;
  } else {
    __half* E = (__half*)Ep;
    __half h[4], l[4];
#pragma unroll
    for (int u=0;u<4;u++) hsp(vv[u], h[u], l[u]);
    uint2 ph = *(uint2*)h, pl = *(uint2*)l;
    if (MODE==2){
      size_t b = (size_t)r*2*C + cc;
      *(uint2*)(E + b)     = ph;
      *(uint2*)(E + b + C) = pl;
    } else {
      *(uint2*)(E + (size_t)r*C + cc) = ph;
    }
  }
}
// bf16 ext of S^T for S [DIM,DIM]
template<bool ASIDE>
__global__ __launch_bounds__(256)
void convT_k(const float* __restrict__ S, bf16* __restrict__ E){
  __shared__ float t[32][33];
  const int bx = blockIdx.x*32, by = blockIdx.y*32;
  const int tx = threadIdx.x&31, ty = threadIdx.x>>5;
  for (int r=0;r<32;r+=8) t[ty+r][tx] = S[(size_t)(by+ty+r)*DIM + bx+tx];
  __syncthreads();
  for (int r=0;r<32;r+=8){
    float v = t[ty+r][tx];
    bf16 h, l; bsp(v, h, l);
    size_t b = (size_t)(bx+tx)*3*DIM + (by+ty+r);
    E[b] = h;
    E[b + DIM]   = ASIDE ? l : h;
    E[b + 2*DIM] = ASIDE ? h : l;
  }
}

__global__ __launch_bounds__(256)
void prep_k(const float* __restrict__ Pq, const float* __restrict__ Wv,
            const float* __restrict__ Wk, const float* __restrict__ Wq,
            const float* __restrict__ bq, const float* __restrict__ bk,
            const float* __restrict__ bv,
            float* __restrict__ U, float* __restrict__ pbv, float* __restrict__ c0)
{
  __shared__ float srow[DIM];
  int b = blockIdx.x, tid = threadIdx.x;
  if (b < 34){
    const float* src = (b<32) ? Pq + b*DIM : ((b==32) ? bq : bk);
    const float* W   = (b<32) ? Wv : ((b==32) ? Wk : Wq);
    for (int e=tid;e<DIM;e+=256) srow[e]=src[e];
    __syncthreads();
    for (int d=tid; d<DIM; d+=256){
      float acc=0.f;
      for (int e=0;e<DIM;e++) acc += srow[e]*W[(size_t)e*DIM+d];
      U[(size_t)b*DIM+d]=acc;
    }
  } else if (b==34){
    int w = tid>>5, l = tid&31;
    for (int p=w; p<32; p+=8){
      float acc=0.f;
      for (int d=l; d<DIM; d+=32) acc += Pq[p*DIM+d]*bv[d];
      for (int o=16;o;o>>=1) acc += __shfl_down_sync(0xffffffffu, acc, o);
      if (l==0) pbv[p]=acc;
    }
  } else {
    __shared__ float red[256];
    float acc=0.f;
    for (int d=tid; d<DIM; d+=256) acc += bq[d]*bk[d];
    red[tid]=acc; __syncthreads();
    for (int s=128; s>0; s>>=1){ if (tid<s) red[tid]+=red[tid+s]; __syncthreads(); }
    if (tid==0) c0[0]=red[0];
  }
}

// writes Z directly as fp16 A2 (h,l)
__global__ __launch_bounds__(256)
void token_k(const float* __restrict__ A, const float* __restrict__ CA,
             const float* __restrict__ GA, const float* __restrict__ CB,
             const float* __restrict__ tkw, const float* __restrict__ pbv,
             const float* __restrict__ c0p, __half* __restrict__ Ze)
{
  extern __shared__ __align__(16) char smraw[];
  float* sA = (float*)smraw; float* sC = sA + 8192;
  __shared__ float sGA[8][NU];
  __shared__ float sS[64], sAttn[64], sNps[32][8], sFa[8], sW[8], sScore[32];
  const int t = blockIdx.x, tid = threadIdx.x;
  const size_t base = (size_t)t*8*DIM;
  const float4* A4 = (const float4*)(A + base);
  const float4* C4 = (const float4*)(CA + base);
  float4* sA4 = (float4*)sA; float4* sC4 = (float4*)sC;
  for (int i=tid; i<2048; i+=256){ sA4[i]=A4[i]; sC4[i]=C4[i]; }
  for (int i=tid; i<8*NU; i+=256) sGA[i/NU][i%NU] = GA[(size_t)(t*8 + i/NU)*NU + i%NU];
  __syncthreads();
  int warp = tid>>5, lane = tid&31;
  for (int p8=0;p8<8;p8++){
    int pair = warp*8+p8;
    const float* ai = sA + (pair>>3)*DIM;
    const float* cj = sC + (pair&7)*DIM;
    float acc=0.f;
    for (int d=lane; d<DIM; d+=32) acc += ai[d]*cj[d];
    for (int o=16;o;o>>=1) acc += __shfl_xor_sync(0xffffffffu, acc, o);
    if (lane==0) sS[pair]=acc;
  }
  __syncthreads();
  float c0 = c0p[0];
  if (warp==0 && lane<8){
    int i=lane;
    float s[8], mx=-1e30f;
    for (int j=0;j<8;j++){ s[j]=SCL*(sS[i*8+j]+sGA[j][32]+sGA[i][33]+c0); mx=fmaxf(mx,s[j]); }
    float sum=0.f;
    for (int j=0;j<8;j++){ s[j]=expf(s[j]-mx); sum+=s[j]; }
    float inv=1.f/sum;
    for (int j=0;j<8;j++) sAttn[i*8+j]=s[j]*inv;
  }
  __syncthreads();
  if (warp==1){
    int p=lane;
    const float* w8 = tkw + (size_t)t*8;
    float nb=0.f;
    for (int i=0;i<8;i++){
      float acc=0.f;
      for (int j=0;j<8;j++) acc += sAttn[i*8+j]*sGA[j][p];
      float nps = SCL*(acc + pbv[p]);
      sNps[p][i]=nps; nb += nps * w8[i];
    }
    sScore[p] = 0.5f*nb + 0.5f*CB[(size_t)t*32+p];
  }
  __syncthreads();
  if (tid==0){
    int sel[4]; float sv[4]; unsigned used=0u;
    for (int r2=0;r2<4;r2++){
      float best=-1e30f; int bi=0;
      for (int p=0;p<32;p++) if(!((used>>p)&1u) && sScore[p]>best){best=sScore[p];bi=p;}
      used |= 1u<<bi; sel[r2]=bi; sv[r2]=best;
    }
    float mx=sv[0], tw[4], sum=0.f;
    for(int r2=0;r2<4;r2++){ tw[r2]=expf(sv[r2]-mx); sum+=tw[r2]; }
    float fa[8]={0,0,0,0,0,0,0,0};
    for(int r2=0;r2<4;r2++){
      int p=sel[r2];
      float m2=-1e30f;
      for(int k=0;k<8;k++) m2=fmaxf(m2,sNps[p][k]);
      float e[8], s2=0.f;
      for(int k=0;k<8;k++){ e[k]=expf(sNps[p][k]-m2); s2+=e[k]; }
      float inv=(tw[r2]/sum)/s2;
      for(int k=0;k<8;k++) fa[k]+=e[k]*inv;
    }
    for(int k=0;k<8;k++) sFa[k]=fa[k];
  }
  __syncthreads();
  if (tid<8){
    float w=0.f;
    for(int i=0;i<8;i++) w += sFa[i]*sAttn[i*8+tid];
    sW[tid]=w;
  }
  __syncthreads();
  for (int d=tid; d<DIM; d+=256){
    float acc=0.f;
    for(int j=0;j<8;j++) acc += sW[j]*sA[j*DIM+d];
    __half h, l; hsp(acc, h, l);
    size_t b = (size_t)t*2*DIM + d;
    Ze[b] = h; Ze[b + DIM] = l;
  }
}

#define SM3_128 (3*(128+128)*144)
#define SM3_64  (3*(128+64)*144)
extern "C" void kernel_launch(void* const* d_in, const int* in_sizes, int n_in,
                              void* d_out, int out_size) {
  const float* x   = (const float*)d_in[0];
  const float* tkw = (const float*)d_in[3];
  const float* A   = (const float*)d_in[4];
  const float* ctx = (const float*)d_in[5];
  const float* Wq  = (const float*)d_in[6];
  const float* bq  = (const float*)d_in[7];
  const float* Wk  = (const float*)d_in[8];
  const float* bk  = (const float*)d_in[9];
  const float* Wv  = (const float*)d_in[10];
  const float* bv  = (const float*)d_in[11];
  const float* Pq  = (const float*)d_in[12];
  const float* Wup = (const float*)d_in[13];
  const float* bup = (const float*)d_in[14];
  const float* Wdn = (const float*)d_in[15];
  const float* bdn = (const float*)d_in[16];
  float* out = (float*)d_out;

  float *pCA,*pG,*pCB,*pU,*ppbv,*pc0;
  __half *pA,*pCU,*pZe,*pWv,*pCO,*pWu,*pH,*pWd;
  bf16 *pWqt,*pWkt,*pcx,*pPq;
  cudaGetSymbolAddress((void**)&pCA,g_CA); cudaGetSymbolAddress((void**)&pG,g_G);
  cudaGetSymbolAddress((void**)&pCB,g_CB);
  cudaGetSymbolAddress((void**)&pU,g_U);   cudaGetSymbolAddress((void**)&ppbv,g_pbv);
  cudaGetSymbolAddress((void**)&pc0,g_c0);
  cudaGetSymbolAddress((void**)&pA,e_A);   cudaGetSymbolAddress((void**)&pWqt,e_Wq);
  cudaGetSymbolAddress((void**)&pWkt,e_Wk);cudaGetSymbolAddress((void**)&pCU,e_CU);
  cudaGetSymbolAddress((void**)&pcx,e_cx);
  cudaGetSymbolAddress((void**)&pPq,e_Pq); cudaGetSymbolAddress((void**)&pZe,e_Z);
  cudaGetSymbolAddress((void**)&pWv,e_Wv); cudaGetSymbolAddress((void**)&pCO,e_CO);
  cudaGetSymbolAddress((void**)&pWu,e_Wu); cudaGetSymbolAddress((void**)&pH,e_H);
  cudaGetSymbolAddress((void**)&pWd,e_Wd);

  cudaFuncSetAttribute(lg_k<128,1,6>, cudaFuncAttributeMaxDynamicSharedMemorySize, SM3_128);
  cudaFuncSetAttribute(lg_k<128,1,7>, cudaFuncAttributeMaxDynamicSharedMemorySize, SM3_128);
  cudaFuncSetAttribute(lg_k<128,1,8>, cudaFuncAttributeMaxDynamicSharedMemorySize, SM3_128);
  cudaFuncSetAttribute(lg_k<128,1,5>, cudaFuncAttributeMaxDynamicSharedMemorySize, SM3_128);
  cudaFuncSetAttribute(lg_k<64,0,0>,  cudaFuncAttributeMaxDynamicSharedMemorySize, SM3_64);
  cudaFuncSetAttribute(lg_k<64,0,1>,  cudaFuncAttributeMaxDynamicSharedMemorySize, SM3_64);
  cudaFuncSetAttribute(token_k, cudaFuncAttributeMaxDynamicSharedMemorySize, 65536);

  prep_k<<<36,256>>>(Pq, Wv, Wk, Wq, bq, bk, bv, pU, ppbv, pc0);
  convT_k<true ><<<dim3(32,32),256>>>(Wq, pWqt);
  convT_k<false><<<dim3(32,32),256>>>(Wk, pWkt);
  // C = Wq^T Wk (bf16 3-term) -> fp16 plain into e_CU rows 0-1023
  lg_k<64,0,1><<<dim3(16,8),256,SM3_64>>>(pWqt, pWkt, 3072, 3072, DIM, DIM, nullptr, nullptr, (bf16*)pCU, nullptr, nullptr);
  // U' -> fp16 plain into e_CU rows 1024-1057
  conv_k<3><<<34, 256>>>(pU, pCU + (size_t)1024*DIM, DIM, (long)NU*DIM/4);
  // A -> fp16 A2 (h,l)
  conv_k<2><<<MA, 256>>>(A, pA, DIM, (long)MA*DIM/4);
  // [CA | G] = A @ [C;U']^T (fp16 2-term, Ka=2048 Kb=1024, split epilogue)
  lg_k<128,1,6><<<dim3(9,256),256,SM3_128>>>(pA, pCU, 2048, 1024, 1058, 1058, pCA, pG, nullptr, nullptr, nullptr);
  conv_k<0><<<TOK, 256>>>(ctx, pcx, DIM, (long)TOK*DIM/4);
  conv_k<1><<<32, 256>>>(Pq, pPq, DIM, (long)32*DIM/4);
  // CB = ctx @ Pq^T (bf16 3-term, fp32 out)
  lg_k<64,0,0><<<dim3(1,32),256,SM3_64>>>(pcx, pPq, 3072, 3072, 32, 32, pCB, nullptr, nullptr, nullptr, nullptr);
  // token -> Z fp16 A2 directly
  token_k<<<TOK,256,65536>>>(A, pCA, pG, pCB, tkw, ppbv, pc0, pZe);
  conv_k<3><<<DIM, 256>>>(Wv, pWv, DIM, (long)DIM*DIM/4);
  // CO = Z @ Wv^T + bv + x -> fp16 A2 (2-term, Ka=2048 Kb=1024)
  lg_k<128,1,7><<<dim3(8,32),256,SM3_128>>>(pZe, pWv, 2048, 1024, DIM, DIM, nullptr, nullptr, (bf16*)pCO, bv, x);
  conv_k<3><<<FDIM, 256>>>(Wup, pWu, DIM, (long)FDIM*DIM/4);
  // H = gelu(CO @ Wup^T + bup) -> fp16 A2 (2-term)
  lg_k<128,1,8><<<dim3(32,32),256,SM3_128>>>(pCO, pWu, 2048, 1024, FDIM, FDIM, nullptr, nullptr, (bf16*)pH, bup, nullptr);
  conv_k<3><<<DIM*4, 256>>>(Wdn, pWd, FDIM, (long)DIM*FDIM/4);
  // out = H @ Wdn^T + bdn (fp16 2-term, Ka=8192 Kb=4096, fp32 out)
  lg_k<128,1,5><<<dim3(8,32),256,SM3_128>>>(pH, pWd, 8192, 4096, DIM, DIM, out, nullptr, nullptr, bdn, nullptr);
}

// round 16
// speedup vs baseline: 1.4889x; 1.4889x over previous
#include <cuda_runtime.h>
#include <cuda_bf16.h>
#include <cuda_fp16.h>
#include <cstdint>
#include <math.h>
#define DIM 1024
#define TOK 4096
#define MA 32768
#define NU 34
#define FDIM 4096
#define SCL 0.03125f
typedef __nv_bfloat16 bf16;

__device__ float g_CA[(size_t)MA*DIM];
__device__ float g_G [(size_t)MA*NU];
__device__ float g_CB[(size_t)TOK*32];
__device__ float g_U [(size_t)NU*DIM];
__device__ float g_pbv[32], g_c0[1];
__device__ __align__(256) __half e_A [(size_t)MA*2*DIM];   // fp16 A2 (h,l)
__device__ __align__(256) __half e_CU[(size_t)1152*DIM];   // fp16 plain: rows 0-1023 C, 1024-1057 U'
__device__ __align__(256) bf16 e_Wq[(size_t)DIM*3*DIM];
__device__ __align__(256) bf16 e_Wk[(size_t)DIM*3*DIM];
__device__ __align__(256) __half e_Z [(size_t)TOK*2*DIM];   // fp16 A2
__device__ __align__(256) __half e_Wv[(size_t)DIM*DIM];     // fp16 plain
__device__ __align__(256) __half e_CO[(size_t)TOK*2*DIM];   // fp16 A2
__device__ __align__(256) __half e_Wu[(size_t)FDIM*DIM];    // fp16 plain
__device__ __align__(256) __half e_H [(size_t)TOK*2*FDIM];  // fp16 A2
__device__ __align__(256) __half e_Wd[(size_t)DIM*FDIM];    // fp16 plain

__device__ __forceinline__ uint32_t smem_u32(const void* p){
  uint32_t a;
  asm("{ .reg .u64 t; cvta.to.shared.u64 t, %1; cvt.u32.u64 %0, t; }" : "=r"(a) : "l"(p));
  return a;
}
__device__ __forceinline__ void cpa16(uint32_t s, const void* g){
  asm volatile("cp.async.cg.shared.global [%0], [%1], 16;\n" :: "r"(s), "l"(g));
}
// DT 0=bf16, 1=fp16
template<int DT>
__device__ __forceinline__ void mma_t(float c[4], const uint32_t a[4], const uint32_t b[2]){
  if (DT==0)
    asm volatile(
      "mma.sync.aligned.m16n8k16.row.col.f32.bf16.bf16.f32 "
      "{%0,%1,%2,%3}, {%4,%5,%6,%7}, {%8,%9}, {%0,%1,%2,%3};\n"
      : "+f"(c[0]), "+f"(c[1]), "+f"(c[2]), "+f"(c[3])
      : "r"(a[0]), "r"(a[1]), "r"(a[2]), "r"(a[3]), "r"(b[0]), "r"(b[1]));
  else
    asm volatile(
      "mma.sync.aligned.m16n8k16.row.col.f32.f16.f16.f32 "
      "{%0,%1,%2,%3}, {%4,%5,%6,%7}, {%8,%9}, {%0,%1,%2,%3};\n"
      : "+f"(c[0]), "+f"(c[1]), "+f"(c[2]), "+f"(c[3])
      : "r"(a[0]), "r"(a[1]), "r"(a[2]), "r"(a[3]), "r"(b[0]), "r"(b[1]));
}
#define LDSM4(r, a) \
  asm volatile("ldmatrix.sync.aligned.m8n8.x4.shared.b16 {%0,%1,%2,%3}, [%4];" \
    : "=r"((r)[0]),"=r"((r)[1]),"=r"((r)[2]),"=r"((r)[3]) : "r"(a))
__device__ __forceinline__ void bsp(float v, bf16 &h, bf16 &l){
  h = __float2bfloat16_rn(v); l = __float2bfloat16_rn(v - __bfloat162float(h));
}
__device__ __forceinline__ void hsp(float v, __half &h, __half &l){
  h = __float2half_rn(v); l = __float2half_rn(v - __half2float(h));
}

// EPI: 0 fp32 | 1 fp16-plain | 5 +bias->fp32 | 6 split CA/G fp32 | 7 +bias+X2->fp16A2 | 8 gelu(+bias)->fp16A2
template<int EPI>
__device__ __forceinline__ void emit(float v, int m, int col, int N,
                                     float* Cf, float* Cf2, bf16* Ce,
                                     const float* bias, const float* X2){
  if (EPI==6){
    if (col < DIM) Cf[(size_t)m*DIM + col] = v;
    else Cf2[(size_t)m*NU + (col-DIM)] = v;
    return;
  }
  if (EPI==1){ ((__half*)Ce)[(size_t)m*N + col] = __float2half_rn(v); return; }
  if (EPI==5){ Cf[(size_t)m*N + col] = v + bias[col]; return; }
  if (EPI==0){ Cf[(size_t)m*N + col] = v; return; }
  if (EPI==7) v += bias[col] + X2[(size_t)m*N + col];
  else { v += bias[col]; v = 0.5f*v*(1.0f + erff(v*0.70710678f)); }
  __half h, l; hsp(v, h, l);
  __half* E = (__half*)Ce;
  size_t b = (size_t)m*2*N;
  E[b + col] = h; E[b + N + col] = l;
}

// C[m,n] = sum over Ka of A[m,k]*B[n,k mod Kb]; 2-byte K-major operands.
// 3-stage cp.async, ldmatrix, 144B rows. Ka%64==0, Kb%64==0, Ka<=2*Kb.
template<int BN, int DT, int EPI>
__global__ __launch_bounds__(256,2)
void lg_k(const void* __restrict__ Av, const void* __restrict__ Bv,
          int Ka, int Kb, int N, int Nb,
          float* __restrict__ Cf, float* __restrict__ Cf2, bf16* __restrict__ Ce,
          const float* __restrict__ bias, const float* __restrict__ X2)
{
  const bf16* A = (const bf16*)Av; const bf16* B = (const bf16*)Bv;
  constexpr int ROWB  = 144;
  constexpr int ATILEB= 128*ROWB;
  constexpr int STAGEB= (128+BN)*ROWB;
  constexpr int CHT   = (128+BN)*8/256;
  constexpr int WN    = BN/2;
  constexpr int NT2   = WN/16;
  extern __shared__ __align__(16) char smraw[];
  const int tid = threadIdx.x;
  const int mBase = blockIdx.y*128, nBase = blockIdx.x*BN;
  const uint32_t smu = smem_u32(smraw);
  const int nK = Ka/64;

  uint32_t choff[CHT]; const bf16* gp[CHT]; bool val[CHT], isA_[CHT];
#pragma unroll
  for (int i=0;i<CHT;i++){
    const int c = tid + i*256;
    const int row = c>>3, kc = c&7;
    const bool isA = row < 128;
    const int lrow = isA ? row : row-128;
    choff[i] = (isA ? 0 : ATILEB) + lrow*ROWB + kc*16;
    const int gr = isA ? (mBase+row) : (nBase+lrow);
    gp[i] = (isA ? A + (size_t)gr*Ka : B + (size_t)gr*Kb) + kc*8;
    isA_[i] = isA;
    val[i] = isA || (nBase+lrow) < Nb;
    if (!val[i]){
      uint4 z = {0u,0u,0u,0u};
#pragma unroll
      for (int st=0; st<3; st++) *(uint4*)(smraw + st*STAGEB + choff[i]) = z;
    }
  }
  auto loadStage = [&](int st){
    if (st < nK){
      const uint32_t b = smu + (st%3)*STAGEB;
      const int koA = st*64;
      const int koB = (koA >= Kb) ? koA - Kb : koA;
#pragma unroll
      for (int i=0;i<CHT;i++) if (val[i]) cpa16(b + choff[i], gp[i] + (isA_[i]?koA:koB));
    }
    asm volatile("cp.async.commit_group;\n":::"memory");
  };

  float acc[2][WN/8][4];
#pragma unroll
  for (int a=0;a<2;a++)
#pragma unroll
    for (int b=0;b<WN/8;b++)
#pragma unroll
      for (int c=0;c<4;c++) acc[a][b][c]=0.f;

  const int warp = tid>>5, lane = tid&31;
  const int wm = (warp>>1)*32, wn = (warp&1)*WN;
  uint32_t aoff[2], boff[NT2];
#pragma unroll
  for (int mt=0;mt<2;mt++)
    aoff[mt] = (uint32_t)(wm + mt*16 + (lane&7) + ((lane>>3)&1)*8)*ROWB + ((lane>>4)&1)*16;
#pragma unroll
  for (int n2=0;n2<NT2;n2++)
    boff[n2] = ATILEB + (uint32_t)(wn + n2*16 + (lane&7) + ((lane>>4)&1)*8)*ROWB + ((lane>>3)&1)*16;

  loadStage(0); loadStage(1);
  for (int kt=0; kt<nK; ++kt){
    asm volatile("cp.async.wait_group 1;\n":::"memory");
    __syncthreads();
    loadStage(kt+2);
    const uint32_t base = smu + (kt%3)*STAGEB;
#pragma unroll
    for (int ks=0; ks<4; ++ks){
      const uint32_t ko = ks*32;
      uint32_t a[2][4];
#pragma unroll
      for (int mt=0;mt<2;mt++) LDSM4(a[mt], base + aoff[mt] + ko);
#pragma unroll
      for (int n2=0;n2<NT2;n2++){
        uint32_t b[4];
        LDSM4(b, base + boff[n2] + ko);
#pragma unroll
        for (int mt=0;mt<2;mt++){
          mma_t<DT>(acc[mt][2*n2],   a[mt], b);
          mma_t<DT>(acc[mt][2*n2+1], a[mt], b+2);
        }
      }
    }
  }

  const int r = lane>>2, c2 = (lane&3)*2;
#pragma unroll
  for (int mt=0;mt<2;mt++){
#pragma unroll
    for (int nt=0; nt<WN/8; nt++){
      const int row = mBase + wm + mt*16 + r;
      const int col = nBase + wn + nt*8 + c2;
      if (col < N){
        emit<EPI>(acc[mt][nt][0], row, col, N, Cf, Cf2, Ce, bias, X2);
        emit<EPI>(acc[mt][nt][2], row+8, col, N, Cf, Cf2, Ce, bias, X2);
      }
      if (col+1 < N){
        emit<EPI>(acc[mt][nt][1], row, col+1, N, Cf, Cf2, Ce, bias, X2);
        emit<EPI>(acc[mt][nt][3], row+8, col+1, N, Cf, Cf2, Ce, bias, X2);
      }
    }
  }
}

// MODE: 2 fp16 A2(h,l) stride2C | 3 fp16 plain strideC
template<int MODE>
__global__ __launch_bounds__(256)
void conv_k(const float* __restrict__ S, void* __restrict__ Ep, int C, long n4){
  long i = (long)blockIdx.x*256 + threadIdx.x;
  if (i >= n4) return;
  int c4 = C/4;
  int r = (int)(i / c4), cc = (int)(i % c4) * 4;
  float4 v = ((const float4*)S)[i];
  float vv[4] = {v.x, v.y, v.z, v.w};
  __half* E = (__half*)Ep;
  __half h[4], l[4];
#pragma unroll
  for (int u=0;u<4;u++) hsp(vv[u], h[u], l[u]);
  uint2 ph = *(uint2*)h, pl = *(uint2*)l;
  if (MODE==2){
    size_t b = (size_t)r*2*C + cc;
    *(uint2*)(E + b)     = ph;
    *(uint2*)(E + b + C) = pl;
  } else {
    *(uint2*)(E + (size_t)r*C + cc) = ph;
  }
}
// bf16 ext of S^T for S [DIM,DIM]
template<bool ASIDE>
__global__ __launch_bounds__(256)
void convT_k(const float* __restrict__ S, bf16* __restrict__ E){
  __shared__ float t[32][33];
  const int bx = blockIdx.x*32, by = blockIdx.y*32;
  const int tx = threadIdx.x&31, ty = threadIdx.x>>5;
  for (int r=0;r<32;r+=8) t[ty+r][tx] = S[(size_t)(by+ty+r)*DIM + bx+tx];
  __syncthreads();
  for (int r=0;r<32;r+=8){
    float v = t[ty+r][tx];
    bf16 h, l; bsp(v, h, l);
    size_t b = (size_t)(bx+tx)*3*DIM + (by+ty+r);
    E[b] = h;
    E[b + DIM]   = ASIDE ? l : h;
    E[b + 2*DIM] = ASIDE ? h : l;
  }
}

// CB[t][p] = sum_d ctx[t][d]*Pq[p][d], exact fp32
__global__ __launch_bounds__(128)
void cb_k(const float* __restrict__ ctx, const float* __restrict__ Pq,
          float* __restrict__ CB){
  __shared__ float sc[DIM];
  const int t = blockIdx.x, tid = threadIdx.x;
  const int w = tid>>5, l = tid&31;
  const float4* c4 = (const float4*)(ctx + (size_t)t*DIM);
  float4* s4 = (float4*)sc;
  for (int i=tid; i<DIM/4; i+=128) s4[i]=c4[i];
  __syncthreads();
  for (int p=w; p<32; p+=4){
    float acc=0.f;
    const float* pr = Pq + (size_t)p*DIM;
    for (int d=l; d<DIM; d+=32) acc += pr[d]*sc[d];
    for (int o=16;o;o>>=1) acc += __shfl_xor_sync(0xffffffffu, acc, o);
    if (l==0) CB[(size_t)t*32+p]=acc;
  }
}

__global__ __launch_bounds__(256)
void prep_k(const float* __restrict__ Pq, const float* __restrict__ Wv,
            const float* __restrict__ Wk, const float* __restrict__ Wq,
            const float* __restrict__ bq, const float* __restrict__ bk,
            const float* __restrict__ bv,
            float* __restrict__ U, float* __restrict__ pbv, float* __restrict__ c0)
{
  __shared__ float srow[DIM];
  int b = blockIdx.x, tid = threadIdx.x;
  if (b < 34){
    const float* src = (b<32) ? Pq + b*DIM : ((b==32) ? bq : bk);
    const float* W   = (b<32) ? Wv : ((b==32) ? Wk : Wq);
    for (int e=tid;e<DIM;e+=256) srow[e]=src[e];
    __syncthreads();
    for (int d=tid; d<DIM; d+=256){
      float acc=0.f;
      for (int e=0;e<DIM;e++) acc += srow[e]*W[(size_t)e*DIM+d];
      U[(size_t)b*DIM+d]=acc;
    }
  } else if (b==34){
    int w = tid>>5, l = tid&31;
    for (int p=w; p<32; p+=8){
      float acc=0.f;
      for (int d=l; d<DIM; d+=32) acc += Pq[p*DIM+d]*bv[d];
      for (int o=16;o;o>>=1) acc += __shfl_down_sync(0xffffffffu, acc, o);
      if (l==0) pbv[p]=acc;
    }
  } else {
    __shared__ float red[256];
    float acc=0.f;
    for (int d=tid; d<DIM; d+=256) acc += bq[d]*bk[d];
    red[tid]=acc; __syncthreads();
    for (int s=128; s>0; s>>=1){ if (tid<s) red[tid]+=red[tid+s]; __syncthreads(); }
    if (tid==0) c0[0]=red[0];
  }
}

// writes Z directly as fp16 A2 (h,l)
__global__ __launch_bounds__(256)
void token_k(const float* __restrict__ A, const float* __restrict__ CA,
             const float* __restrict__ GA, const float* __restrict__ CB,
             const float* __restrict__ tkw, const float* __restrict__ pbv,
             const float* __restrict__ c0p, __half* __restrict__ Ze)
{
  extern __shared__ __align__(16) char smraw[];
  float* sA = (float*)smraw; float* sC = sA + 8192;
  __shared__ float sGA[8][NU];
  __shared__ float sS[64], sAttn[64], sNps[32][8], sFa[8], sW[8], sScore[32];
  const int t = blockIdx.x, tid = threadIdx.x;
  const size_t base = (size_t)t*8*DIM;
  const float4* A4 = (const float4*)(A + base);
  const float4* C4 = (const float4*)(CA + base);
  float4* sA4 = (float4*)sA; float4* sC4 = (float4*)sC;
  for (int i=tid; i<2048; i+=256){ sA4[i]=A4[i]; sC4[i]=C4[i]; }
  for (int i=tid; i<8*NU; i+=256) sGA[i/NU][i%NU] = GA[(size_t)(t*8 + i/NU)*NU + i%NU];
  __syncthreads();
  int warp = tid>>5, lane = tid&31;
  for (int p8=0;p8<8;p8++){
    int pair = warp*8+p8;
    const float* ai = sA + (pair>>3)*DIM;
    const float* cj = sC + (pair&7)*DIM;
    float acc=0.f;
    for (int d=lane; d<DIM; d+=32) acc += ai[d]*cj[d];
    for (int o=16;o;o>>=1) acc += __shfl_xor_sync(0xffffffffu, acc, o);
    if (lane==0) sS[pair]=acc;
  }
  __syncthreads();
  float c0 = c0p[0];
  if (warp==0 && lane<8){
    int i=lane;
    float s[8], mx=-1e30f;
    for (int j=0;j<8;j++){ s[j]=SCL*(sS[i*8+j]+sGA[j][32]+sGA[i][33]+c0); mx=fmaxf(mx,s[j]); }
    float sum=0.f;
    for (int j=0;j<8;j++){ s[j]=expf(s[j]-mx); sum+=s[j]; }
    float inv=1.f/sum;
    for (int j=0;j<8;j++) sAttn[i*8+j]=s[j]*inv;
  }
  __syncthreads();
  if (warp==1){
    int p=lane;
    const float* w8 = tkw + (size_t)t*8;
    float nb=0.f;
    for (int i=0;i<8;i++){
      float acc=0.f;
      for (int j=0;j<8;j++) acc += sAttn[i*8+j]*sGA[j][p];
      float nps = SCL*(acc + pbv[p]);
      sNps[p][i]=nps; nb += nps * w8[i];
    }
    sScore[p] = 0.5f*nb + 0.5f*CB[(size_t)t*32+p];
  }
  __syncthreads();
  if (tid==0){
    int sel[4]; float sv[4]; unsigned used=0u;
    for (int r2=0;r2<4;r2++){
      float best=-1e30f; int bi=0;
      for (int p=0;p<32;p++) if(!((used>>p)&1u) && sScore[p]>best){best=sScore[p];bi=p;}
      used |= 1u<<bi; sel[r2]=bi; sv[r2]=best;
    }
    float mx=sv[0], tw[4], sum=0.f;
    for(int r2=0;r2<4;r2++){ tw[r2]=expf(sv[r2]-mx); sum+=tw[r2]; }
    float fa[8]={0,0,0,0,0,0,0,0};
    for(int r2=0;r2<4;r2++){
      int p=sel[r2];
      float m2=-1e30f;
      for(int k=0;k<8;k++) m2=fmaxf(m2,sNps[p][k]);
      float e[8], s2=0.f;
      for(int k=0;k<8;k++){ e[k]=expf(sNps[p][k]-m2); s2+=e[k]; }
      float inv=(tw[r2]/sum)/s2;
      for(int k=0;k<8;k++) fa[k]+=e[k]*inv;
    }
    for(int k=0;k<8;k++) sFa[k]=fa[k];
  }
  __syncthreads();
  if (tid<8){
    float w=0.f;
    for(int i=0;i<8;i++) w += sFa[i]*sAttn[i*8+tid];
    sW[tid]=w;
  }
  __syncthreads();
  for (int d=tid; d<DIM; d+=256){
    float acc=0.f;
    for(int j=0;j<8;j++) acc += sW[j]*sA[j*DIM+d];
    __half h, l; hsp(acc, h, l);
    size_t b = (size_t)t*2*DIM + d;
    Ze[b] = h; Ze[b + DIM] = l;
  }
}

#define SM3_128 (3*(128+128)*144)
#define SM3_64  (3*(128+64)*144)
extern "C" void kernel_launch(void* const* d_in, const int* in_sizes, int n_in,
                              void* d_out, int out_size) {
  const float* x   = (const float*)d_in[0];
  const float* tkw = (const float*)d_in[3];
  const float* A   = (const float*)d_in[4];
  const float* ctx = (const float*)d_in[5];
  const float* Wq  = (const float*)d_in[6];
  const float* bq  = (const float*)d_in[7];
  const float* Wk  = (const float*)d_in[8];
  const float* bk  = (const float*)d_in[9];
  const float* Wv  = (const float*)d_in[10];
  const float* bv  = (const float*)d_in[11];
  const float* Pq  = (const float*)d_in[12];
  const float* Wup = (const float*)d_in[13];
  const float* bup = (const float*)d_in[14];
  const float* Wdn = (const float*)d_in[15];
  const float* bdn = (const float*)d_in[16];
  float* out = (float*)d_out;

  float *pCA,*pG,*pCB,*pU,*ppbv,*pc0;
  __half *pA,*pCU,*pZe,*pWv,*pCO,*pWu,*pH,*pWd;
  bf16 *pWqt,*pWkt;
  cudaGetSymbolAddress((void**)&pCA,g_CA); cudaGetSymbolAddress((void**)&pG,g_G);
  cudaGetSymbolAddress((void**)&pCB,g_CB);
  cudaGetSymbolAddress((void**)&pU,g_U);   cudaGetSymbolAddress((void**)&ppbv,g_pbv);
  cudaGetSymbolAddress((void**)&pc0,g_c0);
  cudaGetSymbolAddress((void**)&pA,e_A);   cudaGetSymbolAddress((void**)&pWqt,e_Wq);
  cudaGetSymbolAddress((void**)&pWkt,e_Wk);cudaGetSymbolAddress((void**)&pCU,e_CU);
  cudaGetSymbolAddress((void**)&pZe,e_Z);
  cudaGetSymbolAddress((void**)&pWv,e_Wv); cudaGetSymbolAddress((void**)&pCO,e_CO);
  cudaGetSymbolAddress((void**)&pWu,e_Wu); cudaGetSymbolAddress((void**)&pH,e_H);
  cudaGetSymbolAddress((void**)&pWd,e_Wd);

  cudaFuncSetAttribute(lg_k<128,1,6>, cudaFuncAttributeMaxDynamicSharedMemorySize, SM3_128);
  cudaFuncSetAttribute(lg_k<128,1,7>, cudaFuncAttributeMaxDynamicSharedMemorySize, SM3_128);
  cudaFuncSetAttribute(lg_k<128,1,8>, cudaFuncAttributeMaxDynamicSharedMemorySize, SM3_128);
  cudaFuncSetAttribute(lg_k<128,1,5>, cudaFuncAttributeMaxDynamicSharedMemorySize, SM3_128);
  cudaFuncSetAttribute(lg_k<64,0,1>,  cudaFuncAttributeMaxDynamicSharedMemorySize, SM3_64);
  cudaFuncSetAttribute(token_k, cudaFuncAttributeMaxDynamicSharedMemorySize, 65536);

  prep_k<<<36,256>>>(Pq, Wv, Wk, Wq, bq, bk, bv, pU, ppbv, pc0);
  convT_k<true ><<<dim3(32,32),256>>>(Wq, pWqt);
  convT_k<false><<<dim3(32,32),256>>>(Wk, pWkt);
  // C = Wq^T Wk (bf16 3-term) -> fp16 plain into e_CU rows 0-1023
  lg_k<64,0,1><<<dim3(16,8),256,SM3_64>>>(pWqt, pWkt, 3072, 3072, DIM, DIM, nullptr, nullptr, (bf16*)pCU, nullptr, nullptr);
  // U' -> fp16 plain into e_CU rows 1024-1057
  conv_k<3><<<34, 256>>>(pU, pCU + (size_t)1024*DIM, DIM, (long)NU*DIM/4);
  // A -> fp16 A2 (h,l)
  conv_k<2><<<MA, 256>>>(A, pA, DIM, (long)MA*DIM/4);
  // [CA | G] = A @ [C;U']^T (fp16 2-term, Ka=2048 Kb=1024, split epilogue)
  lg_k<128,1,6><<<dim3(9,256),256,SM3_128>>>(pA, pCU, 2048, 1024, 1058, 1058, pCA, pG, nullptr, nullptr, nullptr);
  // CB = ctx @ Pq^T exact fp32
  cb_k<<<TOK,128>>>(ctx, Pq, pCB);
  // token -> Z fp16 A2 directly
  token_k<<<TOK,256,65536>>>(A, pCA, pG, pCB, tkw, ppbv, pc0, pZe);
  conv_k<3><<<DIM, 256>>>(Wv, pWv, DIM, (long)DIM*DIM/4);
  // CO = Z @ Wv^T + bv + x -> fp16 A2 (2-term, Ka=2048 Kb=1024)
  lg_k<128,1,7><<<dim3(8,32),256,SM3_128>>>(pZe, pWv, 2048, 1024, DIM, DIM, nullptr, nullptr, (bf16*)pCO, bv, x);
  conv_k<3><<<FDIM, 256>>>(Wup, pWu, DIM, (long)FDIM*DIM/4);
  // H = gelu(CO @ Wup^T + bup) -> fp16 A2 (2-term)
  lg_k<128,1,8><<<dim3(32,32),256,SM3_128>>>(pCO, pWu, 2048, 1024, FDIM, FDIM, nullptr, nullptr, (bf16*)pH, bup, nullptr);
  conv_k<3><<<DIM*4, 256>>>(Wdn, pWd, FDIM, (long)DIM*FDIM/4);
  // out = H @ Wdn^T + bdn (fp16 2-term, Ka=8192 Kb=4096, fp32 out)
  lg_k<128,1,5><<<dim3(8,32),256,SM3_128>>>(pH, pWd, 8192, 4096, DIM, DIM, out, nullptr, nullptr, bdn, nullptr);
}